// round 16
// baseline (speedup 1.0000x reference)
#include <cuda_runtime.h>
#include <cuda_fp16.h>

#define NN 10000
#define NE 640000
#define CH 128
#define SLOTS 160
#define NTILE64 ((NN + 63) / 64)
#define EB 160                                     // edge-worker blocks fused into gemm1 launch
#define WPAD 136                                   // W smem row stride in halfs (128 + 8 pad)

// ---------------- device scratch (no allocation allowed) ----------------
__device__ float g_deg[NN];                         // after k_deg: dinv = rsqrt(deg)
__device__ int   g_cur[NN];                         // per-node slot cursor
__device__ __align__(16) int2   g_es[NN * SLOTS];   // padded CSR slots: {src, raw ew bits}
__device__ __align__(16) __half g_W1h[CH * CH];     // fp16 W1
__device__ __align__(16) __half g_W2h[CH * CH];     // fp16 W2
__device__ __align__(16) __half g_b1h[CH];          // fp16 b1
__device__ __align__(16) __half g_h1[NN * CH];      // gemm1 out; k_deg scales to h1' = dinv*h1
__device__ __align__(16) __half g_h2[NN * CH];      // gather1 out
__device__ __align__(16) __half g_h3[NN * CH];      // gemm2 out, pre-scaled by dinv
__device__ float g_t0[NN];                          // stencil partials
__device__ float g_t1[NN];
__device__ float g_t2[NN];
__device__ __align__(16) float  g_vk[3 * CH];       // collapsed conv1d+fc weights
__device__ float g_c0;

// ---------------- helpers ----------------
__device__ __forceinline__ float4 h4tof4(uint2 u) {
    __half2 a = *(__half2*)&u.x;
    __half2 b = *(__half2*)&u.y;
    float2 fa = __half22float2(a);
    float2 fb = __half22float2(b);
    return make_float4(fa.x, fa.y, fb.x, fb.y);
}

__device__ __forceinline__ uint2 f4toh4(float4 v) {
    __half2 a = __floats2half2_rn(v.x, v.y);
    __half2 b = __floats2half2_rn(v.z, v.w);
    uint2 u;
    u.x = *(unsigned*)&a;
    u.y = *(unsigned*)&b;
    return u;
}

__device__ __forceinline__ unsigned f2toh2(float2 f) {
    __half2 h = __floats2half2_rn(f.x, f.y);
    return *(unsigned*)&h;
}

__device__ __forceinline__ void mma16816(float* c, unsigned a0, unsigned a1,
                                         unsigned a2, unsigned a3,
                                         unsigned b0, unsigned b1) {
    asm volatile(
        "mma.sync.aligned.m16n8k16.row.col.f32.f16.f16.f32 "
        "{%0,%1,%2,%3}, {%4,%5,%6,%7}, {%8,%9}, {%0,%1,%2,%3};"
        : "+f"(c[0]), "+f"(c[1]), "+f"(c[2]), "+f"(c[3])
        : "r"(a0), "r"(a1), "r"(a2), "r"(a3), "r"(b0), "r"(b1));
}

__device__ __forceinline__ unsigned relu_badd(unsigned a, unsigned b) {
    __half2 x = __hadd2(*(__half2*)&a, *(__half2*)&b);
    __half2 z = __half2half2(__float2half(0.f));
    x = __hmax2(x, z);
    return *(unsigned*)&x;
}

// ---------------- init: resets + fp16 weight conversions + vk/c0 ---------
__global__ void k_init(const float* __restrict__ W1, const float* __restrict__ b1,
                       const float* __restrict__ W2,
                       const float* __restrict__ cw, const float* __restrict__ cb,
                       const float* __restrict__ fw, const float* __restrict__ fb) {
    int gt = blockIdx.x * blockDim.x + threadIdx.x;
    if (gt < NN) g_cur[gt] = 0;
    if (gt < CH * CH) {
        g_W1h[gt] = __float2half(W1[gt]);
        g_W2h[gt] = __float2half(W2[gt]);
    }
    if (gt < CH) g_b1h[gt] = __float2half(b1[gt]);
    if (gt < 3 * CH) {
        int k = gt >> 7, i = gt & 127;
        float s = 0.f;
        for (int h = 0; h < CH; h++) s += fw[h] * cw[h * (CH * 3) + i * 3 + k];
        g_vk[k * CH + i] = s;
    } else if (gt == 3 * CH) {
        float s = fb[0];
        for (int h = 0; h < CH; h++) s += fw[h] * cb[h];
        g_c0 = s;
    }
}

// ---------------- HMMA GEMM with smem-staged W (R11 shape) ---------------
template <bool RB, bool AF32, bool DSCALE>
__device__ __forceinline__ void gemm_hmma(const void* Ap,
                                          const __half* __restrict__ Wh,
                                          __half* __restrict__ C, int tile,
                                          __half* Ws) {
    int t = threadIdx.x;
    int lane = t & 31;
    int w = t >> 5;

#pragma unroll
    for (int it = 0; it < 16; it++) {
        int idx = t + it * 128;
        int n = idx >> 4, c8 = idx & 15;
        uint4 v = *(const uint4*)(Wh + (size_t)n * CH + c8 * 8);
        *(uint4*)(Ws + n * WPAD + c8 * 8) = v;
    }
    __syncthreads();

    int g = lane >> 2;              // 0..7
    int tc = (lane & 3) * 2;        // 0,2,4,6
    int r0 = tile * 64 + w * 16 + g;
    int r1 = r0 + 8;
    int ra = min(r0, NN - 1);       // clamp (stores are guarded)
    int rb = min(r1, NN - 1);

    unsigned af[8][4];
    if (AF32) {
        const float* A = (const float*)Ap;
#pragma unroll
        for (int k8 = 0; k8 < 8; k8++) {
            int k0 = k8 * 16;
            af[k8][0] = f2toh2(*(const float2*)(A + (size_t)ra * CH + k0 + tc));
            af[k8][1] = f2toh2(*(const float2*)(A + (size_t)rb * CH + k0 + tc));
            af[k8][2] = f2toh2(*(const float2*)(A + (size_t)ra * CH + k0 + tc + 8));
            af[k8][3] = f2toh2(*(const float2*)(A + (size_t)rb * CH + k0 + tc + 8));
        }
    } else {
        const __half* A = (const __half*)Ap;
#pragma unroll
        for (int k8 = 0; k8 < 8; k8++) {
            int k0 = k8 * 16;
            af[k8][0] = *(const unsigned*)(A + (size_t)ra * CH + k0 + tc);
            af[k8][1] = *(const unsigned*)(A + (size_t)rb * CH + k0 + tc);
            af[k8][2] = *(const unsigned*)(A + (size_t)ra * CH + k0 + tc + 8);
            af[k8][3] = *(const unsigned*)(A + (size_t)rb * CH + k0 + tc + 8);
        }
    }
    if (RB) {
#pragma unroll
        for (int k8 = 0; k8 < 8; k8++) {
            int k0 = k8 * 16;
            unsigned blo = *(const unsigned*)(g_b1h + k0 + tc);
            unsigned bhi = *(const unsigned*)(g_b1h + k0 + tc + 8);
            af[k8][0] = relu_badd(af[k8][0], blo);
            af[k8][1] = relu_badd(af[k8][1], blo);
            af[k8][2] = relu_badd(af[k8][2], bhi);
            af[k8][3] = relu_badd(af[k8][3], bhi);
        }
    }

    float acc[16][4];
#pragma unroll
    for (int i = 0; i < 16; i++)
#pragma unroll
        for (int j = 0; j < 4; j++) acc[i][j] = 0.f;

#pragma unroll
    for (int nt = 0; nt < 16; nt++) {
        const __half* wp = Ws + (nt * 8 + g) * WPAD + tc;
#pragma unroll
        for (int k8 = 0; k8 < 8; k8++) {
            unsigned b0 = *(const unsigned*)(wp + k8 * 16);      // LDS.32
            unsigned b1r = *(const unsigned*)(wp + k8 * 16 + 8); // LDS.32
            mma16816(acc[nt], af[k8][0], af[k8][1], af[k8][2], af[k8][3], b0, b1r);
        }
    }

    float d0 = 1.f, d1 = 1.f;
    if (DSCALE) {
        d0 = g_deg[ra];      // dinv of row r0
        d1 = g_deg[rb];
    }

#pragma unroll
    for (int nt = 0; nt < 16; nt++) {
        int col = nt * 8 + tc;
        if (r0 < NN) {
            __half2 h = __floats2half2_rn(acc[nt][0] * d0, acc[nt][1] * d0);
            *(__half2*)(C + (size_t)r0 * CH + col) = h;
        }
        if (r1 < NN) {
            __half2 h = __floats2half2_rn(acc[nt][2] * d1, acc[nt][3] * d1);
            *(__half2*)(C + (size_t)r1 * CH + col) = h;
        }
    }
}

// ---------------- fused: GEMM1 blocks || edge-build blocks ---------------
__global__ void __launch_bounds__(128)
k_fused1(const float* __restrict__ x,
         const int* __restrict__ ei, const float* __restrict__ ew) {
    __shared__ __align__(16) __half Ws[CH * WPAD];
    if (blockIdx.x < NTILE64) {
        gemm_hmma<false, true, false>(x, g_W1h, g_h1, blockIdx.x, Ws);
    } else {
        int gt = (blockIdx.x - NTILE64) * 128 + threadIdx.x;
        for (int i = gt; i * 4 < NE; i += EB * 128) {
            int4   r4 = ((const int4*)ei)[i];
            int4   c4 = ((const int4*)(ei + NE))[i];
            float4 w4 = ((const float4*)ew)[i];
#define EDGE1(RR, CC, WW) do {                                       \
                int p = atomicAdd(&g_cur[CC], 1);                    \
                if (p < SLOTS)                                       \
                    g_es[CC * SLOTS + p] = make_int2(RR, __float_as_int(WW)); \
            } while (0)
            EDGE1(r4.x, c4.x, w4.x);
            EDGE1(r4.y, c4.y, w4.y);
            EDGE1(r4.z, c4.z, w4.z);
            EDGE1(r4.w, c4.w, w4.w);
#undef EDGE1
        }
    }
}

// ---- deg: weighted degree -> dinv, and scale h1 row in place (h1' = d*h1)
__global__ void __launch_bounds__(256)
k_deg() {
    int n = (blockIdx.x * blockDim.x + threadIdx.x) >> 5;
    int lane = threadIdx.x & 31;
    if (n >= NN) return;
    int cnt = g_cur[n];
    if (cnt > SLOTS) cnt = SLOTS;
    const int2* es = (const int2*)(g_es + n * SLOTS);
    float s = 0.f;
    for (int j = lane; j < cnt; j += 32)
        s += __int_as_float(es[j].y);
#pragma unroll
    for (int o = 16; o; o >>= 1) s += __shfl_xor_sync(0xffffffffu, s, o);
    float d = rsqrtf(s + 1.0f);     // + self loop
    if (lane == 0) g_deg[n] = d;
    uint2* row = (uint2*)(g_h1 + (size_t)n * CH);
    float4 v = h4tof4(row[lane]);
    v.x *= d; v.y *= d; v.z *= d; v.w *= d;
    row[lane] = f4toh4(v);
}

__global__ void __launch_bounds__(128)
k_gemm2() {
    __shared__ __align__(16) __half Ws[CH * WPAD];
    gemm_hmma<true, false, true>(g_h2, g_W2h, g_h3, blockIdx.x, Ws);
}

// ---------------- gather: 2 warps per node (edge-split) ------------------
// warp pair per node; warp half 0 takes even 8-edge groups + remainder + own
// row, half 1 takes odd groups. Partials combined via smem. NN % 4 == 0, so
// every block has 4 full nodes (no divergent barrier).
// acc = src'[n] + sum_e w_e * src'[r_e];  agg = dinv[n] * acc
template <bool LAYER1>
__device__ __forceinline__ void gather_split(const __half* __restrict__ src,
                                             __half* __restrict__ dsth,
                                             const float* __restrict__ b2) {
    __shared__ float4 part[4][32];
    int t = threadIdx.x;
    int lane = t & 31;
    int wid = t >> 5;           // 0..7
    int pair = wid >> 1;        // 0..3
    int half = wid & 1;         // 0 or 1
    int n = blockIdx.x * 4 + pair;     // always < NN (grid = NN/4)
    const uint2* s2 = (const uint2*)src;

    float4 acc;
    if (half == 0) acc = h4tof4(s2[n * 32 + lane]);   // own pre-scaled row
    else           acc = make_float4(0.f, 0.f, 0.f, 0.f);

    int cnt = g_cur[n];
    if (cnt > SLOTS) cnt = SLOTS;
    const int4* es4 = (const int4*)(g_es + n * SLOTS);   // 2 slots per int4

    for (int j = half * 8; j + 8 <= cnt; j += 16) {
        int q = j >> 1;
        int4 a0 = es4[q + 0];
        int4 a1 = es4[q + 1];
        int4 a2 = es4[q + 2];
        int4 a3 = es4[q + 3];
        float w0 = __int_as_float(a0.y), w1 = __int_as_float(a0.w);
        float w2 = __int_as_float(a1.y), w3 = __int_as_float(a1.w);
        float w4 = __int_as_float(a2.y), w5 = __int_as_float(a2.w);
        float w6 = __int_as_float(a3.y), w7 = __int_as_float(a3.w);
        uint2 u0 = s2[a0.x * 32 + lane];
        uint2 u1 = s2[a0.z * 32 + lane];
        uint2 u2 = s2[a1.x * 32 + lane];
        uint2 u3 = s2[a1.z * 32 + lane];
        uint2 u4 = s2[a2.x * 32 + lane];
        uint2 u5 = s2[a2.z * 32 + lane];
        uint2 u6 = s2[a3.x * 32 + lane];
        uint2 u7 = s2[a3.z * 32 + lane];
        float4 v0 = h4tof4(u0), v1 = h4tof4(u1), v2 = h4tof4(u2), v3 = h4tof4(u3);
        float4 v4 = h4tof4(u4), v5 = h4tof4(u5), v6 = h4tof4(u6), v7 = h4tof4(u7);
        acc.x = fmaf(w0, v0.x, fmaf(w1, v1.x, fmaf(w2, v2.x, fmaf(w3, v3.x, acc.x))));
        acc.y = fmaf(w0, v0.y, fmaf(w1, v1.y, fmaf(w2, v2.y, fmaf(w3, v3.y, acc.y))));
        acc.z = fmaf(w0, v0.z, fmaf(w1, v1.z, fmaf(w2, v2.z, fmaf(w3, v3.z, acc.z))));
        acc.w = fmaf(w0, v0.w, fmaf(w1, v1.w, fmaf(w2, v2.w, fmaf(w3, v3.w, acc.w))));
        acc.x = fmaf(w4, v4.x, fmaf(w5, v5.x, fmaf(w6, v6.x, fmaf(w7, v7.x, acc.x))));
        acc.y = fmaf(w4, v4.y, fmaf(w5, v5.y, fmaf(w6, v6.y, fmaf(w7, v7.y, acc.y))));
        acc.z = fmaf(w4, v4.z, fmaf(w5, v5.z, fmaf(w6, v6.z, fmaf(w7, v7.z, acc.z))));
        acc.w = fmaf(w4, v4.w, fmaf(w5, v5.w, fmaf(w6, v6.w, fmaf(w7, v7.w, acc.w))));
    }
    if (half == 0) {
        const int2* es2 = (const int2*)(g_es + n * SLOTS);
        for (int j = cnt & ~7; j < cnt; j++) {
            int2 s = es2[j];
            float ws = __int_as_float(s.y);
            float4 v = h4tof4(s2[s.x * 32 + lane]);
            acc.x = fmaf(ws, v.x, acc.x);
            acc.y = fmaf(ws, v.y, acc.y);
            acc.z = fmaf(ws, v.z, acc.z);
            acc.w = fmaf(ws, v.w, acc.w);
        }
    } else {
        part[pair][lane] = acc;
    }
    __syncthreads();
    if (half != 0) return;

    float4 p = part[pair][lane];
    float dc = g_deg[n];            // dinv
    acc.x = (acc.x + p.x) * dc;
    acc.y = (acc.y + p.y) * dc;
    acc.z = (acc.z + p.z) * dc;
    acc.w = (acc.w + p.w) * dc;

    if (LAYER1) {
        ((uint2*)dsth)[n * 32 + lane] = f4toh4(acc);
    } else {
        // fused stencil partials: t_k[n] = dot(vk[:,k], relu(acc + b2))
        float4 bb = ((const float4*)b2)[lane];
        float4 h = make_float4(fmaxf(acc.x + bb.x, 0.f), fmaxf(acc.y + bb.y, 0.f),
                               fmaxf(acc.z + bb.z, 0.f), fmaxf(acc.w + bb.w, 0.f));
        float t0, t1, t2;
        {
            float4 v0 = ((const float4*)g_vk)[0 * 32 + lane];
            float4 v1 = ((const float4*)g_vk)[1 * 32 + lane];
            float4 v2 = ((const float4*)g_vk)[2 * 32 + lane];
            t0 = h.x * v0.x + h.y * v0.y + h.z * v0.z + h.w * v0.w;
            t1 = h.x * v1.x + h.y * v1.y + h.z * v1.z + h.w * v1.w;
            t2 = h.x * v2.x + h.y * v2.y + h.z * v2.z + h.w * v2.w;
        }
#pragma unroll
        for (int o = 16; o; o >>= 1) {
            t0 += __shfl_xor_sync(0xffffffffu, t0, o);
            t1 += __shfl_xor_sync(0xffffffffu, t1, o);
            t2 += __shfl_xor_sync(0xffffffffu, t2, o);
        }
        if (lane == 0) {
            g_t0[n] = t0;
            g_t1[n] = t1;
            g_t2[n] = t2;
        }
    }
}

__global__ void __launch_bounds__(256, 4) k_gather1() {
    gather_split<true>(g_h1, g_h2, nullptr);
}
__global__ void __launch_bounds__(256, 4) k_gather2(const float* __restrict__ b2) {
    gather_split<false>(g_h3, nullptr, b2);
}

// -------- final: out[n] = c0 + t0[n-1] + t1[n] + t2[n+1] ------------------
__global__ void k_final(float* __restrict__ out) {
    int n = blockIdx.x * blockDim.x + threadIdx.x;
    if (n >= NN) return;
    float s = g_c0 + g_t1[n];
    if (n > 0) s += g_t0[n - 1];
    if (n < NN - 1) s += g_t2[n + 1];
    out[n] = s;
}

// ---------------- launch ----------------
extern "C" void kernel_launch(void* const* d_in, const int* in_sizes, int n_in,
                              void* d_out, int out_size) {
    (void)in_sizes; (void)n_in; (void)out_size;
    const float* x  = (const float*)d_in[0];
    const int*   ei = (const int*)d_in[1];     // int64 in reference -> int32 here
    const float* ew = (const float*)d_in[2];
    const float* W1 = (const float*)d_in[3];
    const float* b1 = (const float*)d_in[4];
    const float* W2 = (const float*)d_in[5];
    const float* b2 = (const float*)d_in[6];
    const float* cw = (const float*)d_in[7];
    const float* cb = (const float*)d_in[8];
    const float* fw = (const float*)d_in[9];
    const float* fb = (const float*)d_in[10];
    float* out = (float*)d_out;

    const int TB = 256;

    k_init<<<(CH * CH + TB - 1) / TB, TB>>>(W1, b1, W2, cw, cb, fw, fb);
    k_fused1<<<NTILE64 + EB, 128>>>(x, ei, ew);         // gemm1 (fp32-A HMMA) || edge fill
    k_deg<<<(NN * 32 + TB - 1) / TB, TB>>>();           // dinv + h1 pre-scaling
    k_gather1<<<NN / 4, TB>>>();                        // 2 warps per node
    k_gemm2<<<NTILE64, 128>>>();                        // epilogue scales by dinv[row]
    k_gather2<<<NN / 4, TB>>>(b2);                      // + fused stencil partials
    k_final<<<(NN + TB - 1) / TB, TB>>>(out);
}

// round 17
// speedup vs baseline: 1.0887x; 1.0887x over previous
#include <cuda_runtime.h>
#include <cuda_fp16.h>

#define NN 10000
#define NE 640000
#define CH 128
#define SLOTS 160
#define NTILE64 ((NN + 63) / 64)
#define EB 160                                     // edge-worker blocks fused into gemm1 launch
#define WPAD 136                                   // W smem row stride in halfs (128 + 8 pad)

// ---------------- device scratch (no allocation allowed) ----------------
__device__ float g_deg[NN];                         // after k_deg: dinv = rsqrt(deg)
__device__ int   g_cur[NN];                         // per-node slot cursor
__device__ __align__(16) int2   g_es[NN * SLOTS];   // padded CSR slots: {src, raw ew bits}
__device__ __align__(16) __half g_W1h[CH * CH];     // fp16 W1
__device__ __align__(16) __half g_W2h[CH * CH];     // fp16 W2
__device__ __align__(16) __half g_b1h[CH];          // fp16 b1
__device__ __align__(16) __half g_h1[NN * CH];      // gemm1 out; k_deg scales to h1' = dinv*h1
__device__ __align__(16) __half g_h2[NN * CH];      // gather1 out
__device__ __align__(16) __half g_h3[NN * CH];      // gemm2 out, pre-scaled by dinv
__device__ float g_t0[NN];                          // stencil partials
__device__ float g_t1[NN];
__device__ float g_t2[NN];
__device__ __align__(16) float  g_vk[3 * CH];       // collapsed conv1d+fc weights
__device__ float g_c0;

// ---------------- helpers ----------------
__device__ __forceinline__ float4 h4tof4(uint2 u) {
    __half2 a = *(__half2*)&u.x;
    __half2 b = *(__half2*)&u.y;
    float2 fa = __half22float2(a);
    float2 fb = __half22float2(b);
    return make_float4(fa.x, fa.y, fb.x, fb.y);
}

__device__ __forceinline__ uint2 f4toh4(float4 v) {
    __half2 a = __floats2half2_rn(v.x, v.y);
    __half2 b = __floats2half2_rn(v.z, v.w);
    uint2 u;
    u.x = *(unsigned*)&a;
    u.y = *(unsigned*)&b;
    return u;
}

__device__ __forceinline__ unsigned f2toh2(float2 f) {
    __half2 h = __floats2half2_rn(f.x, f.y);
    return *(unsigned*)&h;
}

__device__ __forceinline__ void mma16816(float* c, unsigned a0, unsigned a1,
                                         unsigned a2, unsigned a3,
                                         unsigned b0, unsigned b1) {
    asm volatile(
        "mma.sync.aligned.m16n8k16.row.col.f32.f16.f16.f32 "
        "{%0,%1,%2,%3}, {%4,%5,%6,%7}, {%8,%9}, {%0,%1,%2,%3};"
        : "+f"(c[0]), "+f"(c[1]), "+f"(c[2]), "+f"(c[3])
        : "r"(a0), "r"(a1), "r"(a2), "r"(a3), "r"(b0), "r"(b1));
}

__device__ __forceinline__ unsigned relu_badd(unsigned a, unsigned b) {
    __half2 x = __hadd2(*(__half2*)&a, *(__half2*)&b);
    __half2 z = __half2half2(__float2half(0.f));
    x = __hmax2(x, z);
    return *(unsigned*)&x;
}

// ---------------- init: resets + fp16 weight conversions + vk/c0 ---------
__global__ void k_init(const float* __restrict__ W1, const float* __restrict__ b1,
                       const float* __restrict__ W2,
                       const float* __restrict__ cw, const float* __restrict__ cb,
                       const float* __restrict__ fw, const float* __restrict__ fb) {
    int gt = blockIdx.x * blockDim.x + threadIdx.x;
    if (gt < NN) g_cur[gt] = 0;
    if (gt < CH * CH) {
        g_W1h[gt] = __float2half(W1[gt]);
        g_W2h[gt] = __float2half(W2[gt]);
    }
    if (gt < CH) g_b1h[gt] = __float2half(b1[gt]);
    if (gt < 3 * CH) {
        int k = gt >> 7, i = gt & 127;
        float s = 0.f;
        for (int h = 0; h < CH; h++) s += fw[h] * cw[h * (CH * 3) + i * 3 + k];
        g_vk[k * CH + i] = s;
    } else if (gt == 3 * CH) {
        float s = fb[0];
        for (int h = 0; h < CH; h++) s += fw[h] * cb[h];
        g_c0 = s;
    }
}

// ---------------- HMMA GEMM with smem-staged W (R11 shape) ---------------
template <bool RB, bool AF32, bool DSCALE>
__device__ __forceinline__ void gemm_hmma(const void* Ap,
                                          const __half* __restrict__ Wh,
                                          __half* __restrict__ C, int tile,
                                          __half* Ws) {
    int t = threadIdx.x;
    int lane = t & 31;
    int w = t >> 5;

#pragma unroll
    for (int it = 0; it < 16; it++) {
        int idx = t + it * 128;
        int n = idx >> 4, c8 = idx & 15;
        uint4 v = *(const uint4*)(Wh + (size_t)n * CH + c8 * 8);
        *(uint4*)(Ws + n * WPAD + c8 * 8) = v;
    }
    __syncthreads();

    int g = lane >> 2;              // 0..7
    int tc = (lane & 3) * 2;        // 0,2,4,6
    int r0 = tile * 64 + w * 16 + g;
    int r1 = r0 + 8;
    int ra = min(r0, NN - 1);       // clamp (stores are guarded)
    int rb = min(r1, NN - 1);

    unsigned af[8][4];
    if (AF32) {
        const float* A = (const float*)Ap;
#pragma unroll
        for (int k8 = 0; k8 < 8; k8++) {
            int k0 = k8 * 16;
            af[k8][0] = f2toh2(*(const float2*)(A + (size_t)ra * CH + k0 + tc));
            af[k8][1] = f2toh2(*(const float2*)(A + (size_t)rb * CH + k0 + tc));
            af[k8][2] = f2toh2(*(const float2*)(A + (size_t)ra * CH + k0 + tc + 8));
            af[k8][3] = f2toh2(*(const float2*)(A + (size_t)rb * CH + k0 + tc + 8));
        }
    } else {
        const __half* A = (const __half*)Ap;
#pragma unroll
        for (int k8 = 0; k8 < 8; k8++) {
            int k0 = k8 * 16;
            af[k8][0] = *(const unsigned*)(A + (size_t)ra * CH + k0 + tc);
            af[k8][1] = *(const unsigned*)(A + (size_t)rb * CH + k0 + tc);
            af[k8][2] = *(const unsigned*)(A + (size_t)ra * CH + k0 + tc + 8);
            af[k8][3] = *(const unsigned*)(A + (size_t)rb * CH + k0 + tc + 8);
        }
    }
    if (RB) {
#pragma unroll
        for (int k8 = 0; k8 < 8; k8++) {
            int k0 = k8 * 16;
            unsigned blo = *(const unsigned*)(g_b1h + k0 + tc);
            unsigned bhi = *(const unsigned*)(g_b1h + k0 + tc + 8);
            af[k8][0] = relu_badd(af[k8][0], blo);
            af[k8][1] = relu_badd(af[k8][1], blo);
            af[k8][2] = relu_badd(af[k8][2], bhi);
            af[k8][3] = relu_badd(af[k8][3], bhi);
        }
    }

    float acc[16][4];
#pragma unroll
    for (int i = 0; i < 16; i++)
#pragma unroll
        for (int j = 0; j < 4; j++) acc[i][j] = 0.f;

#pragma unroll
    for (int nt = 0; nt < 16; nt++) {
        const __half* wp = Ws + (nt * 8 + g) * WPAD + tc;
#pragma unroll
        for (int k8 = 0; k8 < 8; k8++) {
            unsigned b0 = *(const unsigned*)(wp + k8 * 16);      // LDS.32
            unsigned b1r = *(const unsigned*)(wp + k8 * 16 + 8); // LDS.32
            mma16816(acc[nt], af[k8][0], af[k8][1], af[k8][2], af[k8][3], b0, b1r);
        }
    }

    float d0 = 1.f, d1 = 1.f;
    if (DSCALE) {
        d0 = g_deg[ra];      // dinv of row r0
        d1 = g_deg[rb];
    }

#pragma unroll
    for (int nt = 0; nt < 16; nt++) {
        int col = nt * 8 + tc;
        if (r0 < NN) {
            __half2 h = __floats2half2_rn(acc[nt][0] * d0, acc[nt][1] * d0);
            *(__half2*)(C + (size_t)r0 * CH + col) = h;
        }
        if (r1 < NN) {
            __half2 h = __floats2half2_rn(acc[nt][2] * d1, acc[nt][3] * d1);
            *(__half2*)(C + (size_t)r1 * CH + col) = h;
        }
    }
}

// ---------------- fused: GEMM1 blocks || edge-build blocks ---------------
__global__ void __launch_bounds__(128)
k_fused1(const float* __restrict__ x,
         const int* __restrict__ ei, const float* __restrict__ ew) {
    __shared__ __align__(16) __half Ws[CH * WPAD];
    if (blockIdx.x < NTILE64) {
        gemm_hmma<false, true, false>(x, g_W1h, g_h1, blockIdx.x, Ws);
    } else {
        int gt = (blockIdx.x - NTILE64) * 128 + threadIdx.x;
        for (int i = gt; i * 4 < NE; i += EB * 128) {
            int4   r4 = ((const int4*)ei)[i];
            int4   c4 = ((const int4*)(ei + NE))[i];
            float4 w4 = ((const float4*)ew)[i];
#define EDGE1(RR, CC, WW) do {                                       \
                int p = atomicAdd(&g_cur[CC], 1);                    \
                if (p < SLOTS)                                       \
                    g_es[CC * SLOTS + p] = make_int2(RR, __float_as_int(WW)); \
            } while (0)
            EDGE1(r4.x, c4.x, w4.x);
            EDGE1(r4.y, c4.y, w4.y);
            EDGE1(r4.z, c4.z, w4.z);
            EDGE1(r4.w, c4.w, w4.w);
#undef EDGE1
        }
    }
}

// ---- deg: weighted degree -> dinv, and scale h1 row in place (h1' = d*h1)
__global__ void __launch_bounds__(256)
k_deg() {
    int n = (blockIdx.x * blockDim.x + threadIdx.x) >> 5;
    int lane = threadIdx.x & 31;
    if (n >= NN) return;
    int cnt = g_cur[n];
    if (cnt > SLOTS) cnt = SLOTS;
    const int2* es = (const int2*)(g_es + n * SLOTS);
    float s = 0.f;
    for (int j = lane; j < cnt; j += 32)
        s += __int_as_float(es[j].y);
#pragma unroll
    for (int o = 16; o; o >>= 1) s += __shfl_xor_sync(0xffffffffu, s, o);
    float d = rsqrtf(s + 1.0f);     // + self loop
    if (lane == 0) g_deg[n] = d;
    uint2* row = (uint2*)(g_h1 + (size_t)n * CH);
    float4 v = h4tof4(row[lane]);
    v.x *= d; v.y *= d; v.z *= d; v.w *= d;
    row[lane] = f4toh4(v);
}

__global__ void __launch_bounds__(128)
k_gemm2() {
    __shared__ __align__(16) __half Ws[CH * WPAD];
    gemm_hmma<true, false, true>(g_h2, g_W2h, g_h3, blockIdx.x, Ws);
}

// ---------------- gather: warp per node, metadata double-buffered --------
// acc = src'[n] + sum_e w_e * src'[r_e];  agg = dinv[n] * acc
// LAYER1: store agg as fp16 (h2). else: stencil epilogue t_k.
template <bool LAYER1>
__device__ __forceinline__ void gather_body(const __half* __restrict__ src,
                                            __half* __restrict__ dsth,
                                            const float* __restrict__ b2) {
    int n = (blockIdx.x * blockDim.x + threadIdx.x) >> 5;
    int lane = threadIdx.x & 31;
    if (n >= NN) return;
    const uint2* s2 = (const uint2*)src;

    float4 acc = h4tof4(s2[n * 32 + lane]);     // own pre-scaled row

    int cnt = g_cur[n];
    if (cnt > SLOTS) cnt = SLOTS;
    const int4* es4 = (const int4*)(g_es + n * SLOTS);   // 2 slots per int4

    // prime metadata double-buffer (4 int4 = 8 edges)
    int4 m0, m1, m2, m3;
    if (cnt >= 8) {
        m0 = es4[0]; m1 = es4[1]; m2 = es4[2]; m3 = es4[3];
    }
    int j = 0;
    for (; j + 8 <= cnt; j += 8) {
        int4 a0 = m0, a1 = m1, a2 = m2, a3 = m3;
        if (j + 16 <= cnt) {                     // prefetch next group's metadata
            int q = (j >> 1) + 4;
            m0 = es4[q + 0]; m1 = es4[q + 1]; m2 = es4[q + 2]; m3 = es4[q + 3];
        }
        float w0 = __int_as_float(a0.y), w1 = __int_as_float(a0.w);
        float w2 = __int_as_float(a1.y), w3 = __int_as_float(a1.w);
        float w4 = __int_as_float(a2.y), w5 = __int_as_float(a2.w);
        float w6 = __int_as_float(a3.y), w7 = __int_as_float(a3.w);
        uint2 u0 = s2[a0.x * 32 + lane];
        uint2 u1 = s2[a0.z * 32 + lane];
        uint2 u2 = s2[a1.x * 32 + lane];
        uint2 u3 = s2[a1.z * 32 + lane];
        uint2 u4 = s2[a2.x * 32 + lane];
        uint2 u5 = s2[a2.z * 32 + lane];
        uint2 u6 = s2[a3.x * 32 + lane];
        uint2 u7 = s2[a3.z * 32 + lane];
        float4 v0 = h4tof4(u0), v1 = h4tof4(u1), v2 = h4tof4(u2), v3 = h4tof4(u3);
        float4 v4 = h4tof4(u4), v5 = h4tof4(u5), v6 = h4tof4(u6), v7 = h4tof4(u7);
        acc.x = fmaf(w0, v0.x, fmaf(w1, v1.x, fmaf(w2, v2.x, fmaf(w3, v3.x, acc.x))));
        acc.y = fmaf(w0, v0.y, fmaf(w1, v1.y, fmaf(w2, v2.y, fmaf(w3, v3.y, acc.y))));
        acc.z = fmaf(w0, v0.z, fmaf(w1, v1.z, fmaf(w2, v2.z, fmaf(w3, v3.z, acc.z))));
        acc.w = fmaf(w0, v0.w, fmaf(w1, v1.w, fmaf(w2, v2.w, fmaf(w3, v3.w, acc.w))));
        acc.x = fmaf(w4, v4.x, fmaf(w5, v5.x, fmaf(w6, v6.x, fmaf(w7, v7.x, acc.x))));
        acc.y = fmaf(w4, v4.y, fmaf(w5, v5.y, fmaf(w6, v6.y, fmaf(w7, v7.y, acc.y))));
        acc.z = fmaf(w4, v4.z, fmaf(w5, v5.z, fmaf(w6, v6.z, fmaf(w7, v7.z, acc.z))));
        acc.w = fmaf(w4, v4.w, fmaf(w5, v5.w, fmaf(w6, v6.w, fmaf(w7, v7.w, acc.w))));
    }
    const int2* es2 = (const int2*)(g_es + n * SLOTS);
    for (; j < cnt; j++) {
        int2 s = es2[j];
        float ws = __int_as_float(s.y);
        float4 v = h4tof4(s2[s.x * 32 + lane]);
        acc.x = fmaf(ws, v.x, acc.x);
        acc.y = fmaf(ws, v.y, acc.y);
        acc.z = fmaf(ws, v.z, acc.z);
        acc.w = fmaf(ws, v.w, acc.w);
    }
    float dc = g_deg[n];            // dinv
    acc.x *= dc; acc.y *= dc; acc.z *= dc; acc.w *= dc;

    if (LAYER1) {
        ((uint2*)dsth)[n * 32 + lane] = f4toh4(acc);
    } else {
        // fused stencil partials: t_k[n] = dot(vk[:,k], relu(acc + b2))
        float4 bb = ((const float4*)b2)[lane];
        float4 h = make_float4(fmaxf(acc.x + bb.x, 0.f), fmaxf(acc.y + bb.y, 0.f),
                               fmaxf(acc.z + bb.z, 0.f), fmaxf(acc.w + bb.w, 0.f));
        float t0, t1, t2;
        {
            float4 v0 = ((const float4*)g_vk)[0 * 32 + lane];
            float4 v1 = ((const float4*)g_vk)[1 * 32 + lane];
            float4 v2 = ((const float4*)g_vk)[2 * 32 + lane];
            t0 = h.x * v0.x + h.y * v0.y + h.z * v0.z + h.w * v0.w;
            t1 = h.x * v1.x + h.y * v1.y + h.z * v1.z + h.w * v1.w;
            t2 = h.x * v2.x + h.y * v2.y + h.z * v2.z + h.w * v2.w;
        }
#pragma unroll
        for (int o = 16; o; o >>= 1) {
            t0 += __shfl_xor_sync(0xffffffffu, t0, o);
            t1 += __shfl_xor_sync(0xffffffffu, t1, o);
            t2 += __shfl_xor_sync(0xffffffffu, t2, o);
        }
        if (lane == 0) {
            g_t0[n] = t0;
            g_t1[n] = t1;
            g_t2[n] = t2;
        }
    }
}

__global__ void __launch_bounds__(256, 4) k_gather1() {
    gather_body<true>(g_h1, g_h2, nullptr);
}
__global__ void __launch_bounds__(256, 4) k_gather2(const float* __restrict__ b2) {
    gather_body<false>(g_h3, nullptr, b2);
}

// -------- final: out[n] = c0 + t0[n-1] + t1[n] + t2[n+1] ------------------
__global__ void k_final(float* __restrict__ out) {
    int n = blockIdx.x * blockDim.x + threadIdx.x;
    if (n >= NN) return;
    float s = g_c0 + g_t1[n];
    if (n > 0) s += g_t0[n - 1];
    if (n < NN - 1) s += g_t2[n + 1];
    out[n] = s;
}

// ---------------- launch ----------------
extern "C" void kernel_launch(void* const* d_in, const int* in_sizes, int n_in,
                              void* d_out, int out_size) {
    (void)in_sizes; (void)n_in; (void)out_size;
    const float* x  = (const float*)d_in[0];
    const int*   ei = (const int*)d_in[1];     // int64 in reference -> int32 here
    const float* ew = (const float*)d_in[2];
    const float* W1 = (const float*)d_in[3];
    const float* b1 = (const float*)d_in[4];
    const float* W2 = (const float*)d_in[5];
    const float* b2 = (const float*)d_in[6];
    const float* cw = (const float*)d_in[7];
    const float* cb = (const float*)d_in[8];
    const float* fw = (const float*)d_in[9];
    const float* fb = (const float*)d_in[10];
    float* out = (float*)d_out;

    const int TB = 256;

    k_init<<<(CH * CH + TB - 1) / TB, TB>>>(W1, b1, W2, cw, cb, fw, fb);
    k_fused1<<<NTILE64 + EB, 128>>>(x, ei, ew);         // gemm1 (fp32-A HMMA) || edge fill
    k_deg<<<(NN * 32 + TB - 1) / TB, TB>>>();           // dinv + h1 pre-scaling
    k_gather1<<<(NN * 32 + TB - 1) / TB, TB>>>();       // warp per node + meta prefetch
    k_gemm2<<<NTILE64, 128>>>();                        // epilogue scales by dinv[row]
    k_gather2<<<(NN * 32 + TB - 1) / TB, TB>>>(b2);     // + fused stencil partials
    k_final<<<(NN + TB - 1) / TB, TB>>>(out);
}